// round 16
// baseline (speedup 1.0000x reference)
#include <cuda_runtime.h>
#include <cuda_fp16.h>
#include <math.h>
#include <stdint.h>

// ---------------------------------------------------------------------------
// graphNet: 4-layer GCN (21->168->84->42->21) + log_softmax.
// Round-16: R15 base (350.8us) + A-resident TC GEMM: each block stages its
// full 128xK A slice in dynamic smem ONCE and sweeps all N-tiles, removing
// the M/32-fold A re-read from L2 (layer 2 was 3x67MB). Everything else
// unchanged: atomic-free scatter, fp16 t2 gather, dense agg mapping.
// ---------------------------------------------------------------------------

#define N_MAX 100000
#define E_MAX 1600000
#define F_MAX 168
#define CSR_MAX (E_MAX + 4 * N_MAX)
#define SCAN_B 1024

struct __align__(8) Edge { int src; float w; };

__device__ float  g_bufA[(size_t)N_MAX * F_MAX];
__device__ float  g_bufB[(size_t)N_MAX * F_MAX];
__device__ __half g_bufH[(size_t)N_MAX * 84];       // t2 in fp16
__device__ int    g_ideg[N_MAX];
__device__ float  g_dinv[N_MAX];
__device__ int    g_rowbeg[N_MAX];
__device__ int    g_pos[E_MAX];                     // per-edge slot within its row
__device__ int    g_counter[1];
__device__ Edge   g_csr[CSR_MAX];

// ---------------- init / degree ----------------

__global__ void k_init(int* __restrict__ ideg, int* __restrict__ counter, int n) {
    int i = blockIdx.x * blockDim.x + threadIdx.x;
    if (i < n) ideg[i] = 0;
    if (i == 0) counter[0] = 0;
}

// counts degree AND records each edge's position within its dst row
__global__ void k_count_deg(const int* __restrict__ ei, int* __restrict__ ideg,
                            int* __restrict__ pos, int E) {
    int e = blockIdx.x * blockDim.x + threadIdx.x;
    if (e < E) pos[e] = atomicAdd(&ideg[ei[E + e]], 1);
}

// ---------------- fused single-pass offsets ----------------

__global__ void k_offsets(const int* __restrict__ ideg, int* __restrict__ row_beg,
                          float* __restrict__ dinv, Edge* __restrict__ csr,
                          int* __restrict__ counter, int n) {
    __shared__ int s[SCAN_B];
    __shared__ int base_sh;
    int i = blockIdx.x * SCAN_B + threadIdx.x;
    int deg = (i < n) ? ideg[i] : 0;
    int pd = (deg + 3) & ~3;
    s[threadIdx.x] = pd;
    __syncthreads();
#pragma unroll
    for (int off = 1; off < SCAN_B; off <<= 1) {
        int t = (threadIdx.x >= off) ? s[threadIdx.x - off] : 0;
        __syncthreads();
        s[threadIdx.x] += t;
        __syncthreads();
    }
    if (threadIdx.x == SCAN_B - 1) base_sh = atomicAdd(counter, s[SCAN_B - 1]);
    __syncthreads();
    int base = base_sh;
    if (i < n) {
        int beg = base + s[threadIdx.x] - pd;
        row_beg[i] = beg;
        dinv[i] = rsqrtf((float)(deg + 1));
        Edge z; z.src = 0; z.w = 0.f;
        for (int p = deg; p < pd; p++) csr[beg + p] = z;
    }
}

// ---------------- CSR scatter (atomic-free) ----------------

__global__ void k_scatter(const int* __restrict__ ei, const int* __restrict__ row_beg,
                          const int* __restrict__ pos, const float* __restrict__ dinv,
                          Edge* __restrict__ csr, int E) {
    int e = blockIdx.x * blockDim.x + threadIdx.x;
    if (e < E) {
        int s = ei[e];
        int d = ei[E + e];
        float2 rec = make_float2(__int_as_float(s), dinv[s] * dinv[d]);
        *reinterpret_cast<float2*>(&csr[row_beg[d] + pos[e]]) = rec;
    }
}

// ---------------- vector row load helpers ----------------

template <int VW>
__device__ __forceinline__ void ldrow(float (&f)[VW], const float* __restrict__ p) {
    if (VW == 4) { float4 t = *(const float4*)p; f[0]=t.x; f[1]=t.y; f[2]=t.z; f[3]=t.w; }
    else if (VW == 2) { float2 t = *(const float2*)p; f[0]=t.x; f[1]=t.y; }
    else { f[0] = *p; }
}

__device__ __forceinline__ void ldrow_h4(float (&f)[4], const __half* __restrict__ p) {
    uint2 u = *(const uint2*)p;                        // 4 halves, 8B aligned
    float2 a = __half22float2(*reinterpret_cast<const __half2*>(&u.x));
    float2 b = __half22float2(*reinterpret_cast<const __half2*>(&u.y));
    f[0] = a.x; f[1] = a.y; f[2] = b.x; f[3] = b.y;
}

// ---------------- fused CSR aggregation (dense thread mapping, fp32 in) --------

template <int C, int VW, int SIN, int SOUT>
__global__ void k_agg(const float* __restrict__ h, const int* __restrict__ row_beg,
                      const int* __restrict__ ideg,
                      const Edge* __restrict__ csr, const float* __restrict__ dinv,
                      const float* __restrict__ bias, float* __restrict__ out, int n) {
    constexpr int L = C / VW;
    constexpr int TPN = SOUT / VW;
    int t = blockIdx.x * blockDim.x + threadIdx.x;
    int v = t / TPN;
    int r = t - v * TPN;
    if (v >= n) return;

    if (r < L) {
        int beg = row_beg[v];
        int endp = beg + ((ideg[v] + 3) & ~3);
        const int off = r * VW;

        float dv = dinv[v];
        float pvv[VW];
        ldrow<VW>(pvv, h + v * SIN + off);

        float acc[VW];
#pragma unroll
        for (int k = 0; k < VW; k++) acc[k] = 0.f;

        int j = beg;
        for (; j + 8 <= endp; j += 8) {
            int4 e0 = *(const int4*)(csr + j);
            int4 e1 = *(const int4*)(csr + j + 2);
            int4 e2 = *(const int4*)(csr + j + 4);
            int4 e3 = *(const int4*)(csr + j + 6);
            float f[8][VW];
            ldrow<VW>(f[0], h + e0.x * SIN + off);
            ldrow<VW>(f[1], h + e0.z * SIN + off);
            ldrow<VW>(f[2], h + e1.x * SIN + off);
            ldrow<VW>(f[3], h + e1.z * SIN + off);
            ldrow<VW>(f[4], h + e2.x * SIN + off);
            ldrow<VW>(f[5], h + e2.z * SIN + off);
            ldrow<VW>(f[6], h + e3.x * SIN + off);
            ldrow<VW>(f[7], h + e3.z * SIN + off);
            float w[8];
            w[0] = __int_as_float(e0.y); w[1] = __int_as_float(e0.w);
            w[2] = __int_as_float(e1.y); w[3] = __int_as_float(e1.w);
            w[4] = __int_as_float(e2.y); w[5] = __int_as_float(e2.w);
            w[6] = __int_as_float(e3.y); w[7] = __int_as_float(e3.w);
#pragma unroll
            for (int i = 0; i < 8; i++)
#pragma unroll
                for (int k = 0; k < VW; k++) acc[k] = fmaf(w[i], f[i][k], acc[k]);
        }
        if (j < endp) {
            int4 e0 = *(const int4*)(csr + j);
            int4 e1 = *(const int4*)(csr + j + 2);
            float f[4][VW];
            ldrow<VW>(f[0], h + e0.x * SIN + off);
            ldrow<VW>(f[1], h + e0.z * SIN + off);
            ldrow<VW>(f[2], h + e1.x * SIN + off);
            ldrow<VW>(f[3], h + e1.z * SIN + off);
            float w[4];
            w[0] = __int_as_float(e0.y); w[1] = __int_as_float(e0.w);
            w[2] = __int_as_float(e1.y); w[3] = __int_as_float(e1.w);
#pragma unroll
            for (int i = 0; i < 4; i++)
#pragma unroll
                for (int k = 0; k < VW; k++) acc[k] = fmaf(w[i], f[i][k], acc[k]);
        }

        float s2 = dv * dv;
        float* po = out + v * SOUT + off;
#pragma unroll
        for (int k = 0; k < VW; k++) {
            float r2 = fmaf(s2, pvv[k], acc[k]);
            if (bias) r2 = fmaxf(r2 + bias[off + k], 0.f);
            po[k] = r2;
        }
    } else {
        float* po = out + v * SOUT + r * VW;
#pragma unroll
        for (int k = 0; k < VW; k++) po[k] = 0.f;
    }
}

// ---------------- fp16-input aggregation (layer 2: C=84, VW=4, TPN=21) --------

__global__ void k_agg_h(const __half* __restrict__ h,      // stride 84 halves
                        const int* __restrict__ row_beg,
                        const int* __restrict__ ideg,
                        const Edge* __restrict__ csr, const float* __restrict__ dinv,
                        const float* __restrict__ bias, float* __restrict__ out, int n) {
    int t = blockIdx.x * blockDim.x + threadIdx.x;
    int v = t / 21;
    int r = t - v * 21;
    if (v >= n) return;

    int beg = row_beg[v];
    int endp = beg + ((ideg[v] + 3) & ~3);
    const int off = r * 4;

    float dv = dinv[v];
    float pvv[4];
    ldrow_h4(pvv, h + v * 84 + off);

    float acc[4] = {0.f, 0.f, 0.f, 0.f};

    int j = beg;
    for (; j + 8 <= endp; j += 8) {
        int4 e0 = *(const int4*)(csr + j);
        int4 e1 = *(const int4*)(csr + j + 2);
        int4 e2 = *(const int4*)(csr + j + 4);
        int4 e3 = *(const int4*)(csr + j + 6);
        float f[8][4];
        ldrow_h4(f[0], h + e0.x * 84 + off);
        ldrow_h4(f[1], h + e0.z * 84 + off);
        ldrow_h4(f[2], h + e1.x * 84 + off);
        ldrow_h4(f[3], h + e1.z * 84 + off);
        ldrow_h4(f[4], h + e2.x * 84 + off);
        ldrow_h4(f[5], h + e2.z * 84 + off);
        ldrow_h4(f[6], h + e3.x * 84 + off);
        ldrow_h4(f[7], h + e3.z * 84 + off);
        float w[8];
        w[0] = __int_as_float(e0.y); w[1] = __int_as_float(e0.w);
        w[2] = __int_as_float(e1.y); w[3] = __int_as_float(e1.w);
        w[4] = __int_as_float(e2.y); w[5] = __int_as_float(e2.w);
        w[6] = __int_as_float(e3.y); w[7] = __int_as_float(e3.w);
#pragma unroll
        for (int i = 0; i < 8; i++)
#pragma unroll
            for (int k = 0; k < 4; k++) acc[k] = fmaf(w[i], f[i][k], acc[k]);
    }
    if (j < endp) {
        int4 e0 = *(const int4*)(csr + j);
        int4 e1 = *(const int4*)(csr + j + 2);
        float f[4][4];
        ldrow_h4(f[0], h + e0.x * 84 + off);
        ldrow_h4(f[1], h + e0.z * 84 + off);
        ldrow_h4(f[2], h + e1.x * 84 + off);
        ldrow_h4(f[3], h + e1.z * 84 + off);
        float w[4];
        w[0] = __int_as_float(e0.y); w[1] = __int_as_float(e0.w);
        w[2] = __int_as_float(e1.y); w[3] = __int_as_float(e1.w);
#pragma unroll
        for (int i = 0; i < 4; i++)
#pragma unroll
            for (int k = 0; k < 4; k++) acc[k] = fmaf(w[i], f[i][k], acc[k]);
    }

    float s2 = dv * dv;
    float* po = out + v * 84 + off;
#pragma unroll
    for (int k = 0; k < 4; k++) {
        float r2 = fmaf(s2, pvv[k], acc[k]);
        r2 = fmaxf(r2 + bias[off + k], 0.f);
        po[k] = r2;
    }
}

// ---------------- scalar GEMM (layer 4 — exact fp32) ----------------

#define GBM 256
#define GBN 32
#define GBK 16

__global__ void __launch_bounds__(256)
k_gemm(const float* __restrict__ A, const float* __restrict__ W,
       const float* __restrict__ bias, float* __restrict__ Cout,
       int N, int K, int M, int SA, int SC, int fuse_bias_relu) {
    __shared__ float As[GBK][GBM];
    __shared__ float Bs[GBK][GBN];

    int tid = threadIdx.x;
    int bm = blockIdx.x * GBM;
    int bn = blockIdx.y * GBN;
    int ty = tid >> 3;
    int tx = tid & 7;
    int row0 = ty * 8;
    int col0 = tx * 4;

    float acc[8][4];
#pragma unroll
    for (int i = 0; i < 8; i++)
#pragma unroll
        for (int j = 0; j < 4; j++) acc[i][j] = 0.f;

    for (int k0 = 0; k0 < K; k0 += GBK) {
#pragma unroll
        for (int i = 0; i < 4; i++) {
            int lin4 = tid + i * 256;
            int r = lin4 >> 2;
            int kk4 = lin4 & 3;
            int gr = bm + r;
            int gk0 = k0 + kk4 * 4;
            float4 a = make_float4(0.f, 0.f, 0.f, 0.f);
            if (gr < N && gk0 + 3 < SA)
                a = *(const float4*)(A + (size_t)gr * SA + gk0);
            As[kk4 * 4 + 0][r] = a.x;
            As[kk4 * 4 + 1][r] = a.y;
            As[kk4 * 4 + 2][r] = a.z;
            As[kk4 * 4 + 3][r] = a.w;
        }
#pragma unroll
        for (int i = 0; i < 2; i++) {
            int lin = tid + i * 256;
            int r = lin >> 5;
            int c = lin & 31;
            int gk = k0 + r, gc = bn + c;
            Bs[r][c] = (gk < K && gc < M) ? W[(size_t)gk * M + gc] : 0.f;
        }
        __syncthreads();

#pragma unroll
        for (int kk = 0; kk < GBK; kk++) {
            float4 a0 = *(const float4*)&As[kk][row0];
            float4 a1 = *(const float4*)&As[kk][row0 + 4];
            float4 b  = *(const float4*)&Bs[kk][col0];
            float av[8] = {a0.x, a0.y, a0.z, a0.w, a1.x, a1.y, a1.z, a1.w};
            float bv[4] = {b.x, b.y, b.z, b.w};
#pragma unroll
            for (int i = 0; i < 8; i++)
#pragma unroll
                for (int j = 0; j < 4; j++) acc[i][j] = fmaf(av[i], bv[j], acc[i][j]);
        }
        __syncthreads();
    }

#pragma unroll
    for (int i = 0; i < 8; i++) {
        int gr = bm + row0 + i;
        if (gr < N) {
#pragma unroll
            for (int j = 0; j < 4; j++) {
                int gc = bn + col0 + j;
                if (gc < M) {
                    float v = acc[i][j];
                    if (fuse_bias_relu) v = fmaxf(v + bias[gc], 0.f);
                    Cout[(size_t)gr * SC + gc] = v;
                }
            }
        }
    }
}

// ---------------- A-resident tf32 TC GEMM (layers 1, 2, 3) ----------------
// Stages the block's full 128xKP A slice (tf32) in dynamic smem once, then
// sweeps all N-tiles of 32 columns. A read from L2 exactly once per block.

__device__ __forceinline__ uint32_t f2tf32(float x) {
    uint32_t r;
    asm("cvt.rna.tf32.f32 %0, %1;" : "=r"(r) : "f"(x));
    return r;
}

#define TAS 132   // padded smem row stride (words) — conflict pattern as proven

__global__ void __launch_bounds__(128)
k_gemm_tc(const float* __restrict__ A, const float* __restrict__ W,
          const float* __restrict__ bias, float* __restrict__ Cout,
          __half* __restrict__ CoutH,
          int N, int K, int M, int SA, int SC, int fuse_bias_relu) {
    extern __shared__ float AsD[];        // [KP][TAS] flattened: AsD[k*TAS + row]

    int tid = threadIdx.x;
    int warp = tid >> 5;
    int lane = tid & 31;
    int g  = lane >> 2;
    int tg = lane & 3;
    int bm = blockIdx.x * 128;
    int wr = warp * 32;

    int ksteps = (K + 7) >> 3;
    int KP = ksteps << 3;

    // ---- stage A (tf32) : all KP k-rows, zero-fill beyond SA / N ----
    {
        int KPq = KP >> 2;                // float4 groups per row
        for (int idx = tid; idx < 128 * KPq; idx += 128) {
            int r = idx / KPq;
            int q = idx - r * KPq;
            int k0 = q * 4;
            int gr = bm + r;
            float va[4] = {0.f, 0.f, 0.f, 0.f};
            if (gr < N) {
                if (k0 + 3 < SA) {
                    float4 a = *(const float4*)(A + (size_t)gr * SA + k0);
                    va[0] = a.x; va[1] = a.y; va[2] = a.z; va[3] = a.w;
                } else {
#pragma unroll
                    for (int jj = 0; jj < 4; jj++) {
                        int kk = k0 + jj;
                        if (kk < SA) va[jj] = A[(size_t)gr * SA + kk];
                    }
                }
            }
#pragma unroll
            for (int jj = 0; jj < 4; jj++)
                AsD[(k0 + jj) * TAS + r] = __uint_as_float(f2tf32(va[jj]));
        }
    }
    __syncthreads();

    // ---- sweep N-tiles of 32 columns ----
    for (int bn = 0; bn < M; bn += 32) {
        float c[2][4][4];
#pragma unroll
        for (int mt = 0; mt < 2; mt++)
#pragma unroll
            for (int t = 0; t < 4; t++)
#pragma unroll
                for (int q = 0; q < 4; q++) c[mt][t][q] = 0.f;

        for (int ks = 0; ks < ksteps; ks++) {
            int k0 = ks << 3;
            uint32_t bfr[4][2];
#pragma unroll
            for (int t = 0; t < 4; t++) {
                int col = bn + t * 8 + g;
                int r0 = k0 + tg;
                int r1 = r0 + 4;
                float b0 = (r0 < K && col < M) ? W[(size_t)r0 * M + col] : 0.f;
                float b1 = (r1 < K && col < M) ? W[(size_t)r1 * M + col] : 0.f;
                bfr[t][0] = f2tf32(b0);
                bfr[t][1] = f2tf32(b1);
            }

#pragma unroll
            for (int mt = 0; mt < 2; mt++) {
                int r = wr + mt * 16 + g;
                uint32_t a0 = __float_as_uint(AsD[(k0 + tg) * TAS + r]);
                uint32_t a1 = __float_as_uint(AsD[(k0 + tg) * TAS + r + 8]);
                uint32_t a2 = __float_as_uint(AsD[(k0 + tg + 4) * TAS + r]);
                uint32_t a3 = __float_as_uint(AsD[(k0 + tg + 4) * TAS + r + 8]);
#pragma unroll
                for (int t = 0; t < 4; t++) {
                    asm volatile(
                        "mma.sync.aligned.m16n8k8.row.col.f32.tf32.tf32.f32 "
                        "{%0,%1,%2,%3}, {%4,%5,%6,%7}, {%8,%9}, {%0,%1,%2,%3};"
                        : "+f"(c[mt][t][0]), "+f"(c[mt][t][1]),
                          "+f"(c[mt][t][2]), "+f"(c[mt][t][3])
                        : "r"(a0), "r"(a1), "r"(a2), "r"(a3),
                          "r"(bfr[t][0]), "r"(bfr[t][1]));
                }
            }
        }

        // epilogue for this n-tile
#pragma unroll
        for (int mt = 0; mt < 2; mt++) {
#pragma unroll
            for (int t = 0; t < 4; t++) {
                int col = bn + t * 8 + 2 * tg;
                int r0 = bm + wr + mt * 16 + g;
                float v0 = c[mt][t][0], v1 = c[mt][t][1];
                float v2 = c[mt][t][2], v3 = c[mt][t][3];
                if (fuse_bias_relu) {
                    if (col < M) {
                        float bb0 = bias[col];
                        v0 = fmaxf(v0 + bb0, 0.f);
                        v2 = fmaxf(v2 + bb0, 0.f);
                    }
                    if (col + 1 < M) {
                        float bb1 = bias[col + 1];
                        v1 = fmaxf(v1 + bb1, 0.f);
                        v3 = fmaxf(v3 + bb1, 0.f);
                    }
                }
                if (CoutH) {
                    if (col + 1 < M) {
                        if (r0 < N)
                            *(__half2*)(CoutH + (size_t)r0 * SC + col) =
                                __floats2half2_rn(v0, v1);
                        if (r0 + 8 < N)
                            *(__half2*)(CoutH + (size_t)(r0 + 8) * SC + col) =
                                __floats2half2_rn(v2, v3);
                    } else if (col < M) {
                        if (r0 < N) CoutH[(size_t)r0 * SC + col] = __float2half_rn(v0);
                        if (r0 + 8 < N) CoutH[(size_t)(r0 + 8) * SC + col] = __float2half_rn(v2);
                    }
                } else {
                    if (col + 1 < M) {
                        if (r0 < N)
                            *(float2*)(Cout + (size_t)r0 * SC + col) = make_float2(v0, v1);
                        if (r0 + 8 < N)
                            *(float2*)(Cout + (size_t)(r0 + 8) * SC + col) = make_float2(v2, v3);
                    } else if (col < M) {
                        if (r0 < N) Cout[(size_t)r0 * SC + col] = v0;
                        if (r0 + 8 < N) Cout[(size_t)(r0 + 8) * SC + col] = v2;
                    }
                }
            }
        }
    }
}

// ---------------- final: CSR agg + bias + relu + log_softmax (warp/node) --------

__global__ void k_final(const float* __restrict__ t4,       // stride 24
                        const int* __restrict__ row_beg,
                        const int* __restrict__ ideg,
                        const Edge* __restrict__ csr,
                        const float* __restrict__ dinv,
                        const float* __restrict__ b4,
                        float* __restrict__ out_z, float* __restrict__ out_pz, int n) {
    int v = (blockIdx.x * blockDim.x + threadIdx.x) >> 5;
    int lane = threadIdx.x & 31;
    if (v >= n) return;

    float val = -INFINITY;
    if (lane < 21) {
        int beg = row_beg[v];
        int endp = beg + ((ideg[v] + 3) & ~3);
        float dv = dinv[v];
        float selfv = t4[v * 24 + lane];
        float acc = 0.f;

        int j = beg;
        for (; j + 8 <= endp; j += 8) {
            int4 e0 = *(const int4*)(csr + j);
            int4 e1 = *(const int4*)(csr + j + 2);
            int4 e2 = *(const int4*)(csr + j + 4);
            int4 e3 = *(const int4*)(csr + j + 6);
            float f0 = t4[e0.x * 24 + lane];
            float f1 = t4[e0.z * 24 + lane];
            float f2 = t4[e1.x * 24 + lane];
            float f3 = t4[e1.z * 24 + lane];
            float f4 = t4[e2.x * 24 + lane];
            float f5 = t4[e2.z * 24 + lane];
            float f6 = t4[e3.x * 24 + lane];
            float f7 = t4[e3.z * 24 + lane];
            acc = fmaf(__int_as_float(e0.y), f0, acc);
            acc = fmaf(__int_as_float(e0.w), f1, acc);
            acc = fmaf(__int_as_float(e1.y), f2, acc);
            acc = fmaf(__int_as_float(e1.w), f3, acc);
            acc = fmaf(__int_as_float(e2.y), f4, acc);
            acc = fmaf(__int_as_float(e2.w), f5, acc);
            acc = fmaf(__int_as_float(e3.y), f6, acc);
            acc = fmaf(__int_as_float(e3.w), f7, acc);
        }
        if (j < endp) {
            int4 e0 = *(const int4*)(csr + j);
            int4 e1 = *(const int4*)(csr + j + 2);
            float f0 = t4[e0.x * 24 + lane];
            float f1 = t4[e0.z * 24 + lane];
            float f2 = t4[e1.x * 24 + lane];
            float f3 = t4[e1.z * 24 + lane];
            acc = fmaf(__int_as_float(e0.y), f0, acc);
            acc = fmaf(__int_as_float(e0.w), f1, acc);
            acc = fmaf(__int_as_float(e1.y), f2, acc);
            acc = fmaf(__int_as_float(e1.w), f3, acc);
        }
        acc = fmaf(dv * dv, selfv, acc);
        val = fmaxf(acc + b4[lane], 0.f);
    }

    float m = val;
#pragma unroll
    for (int o = 16; o > 0; o >>= 1) m = fmaxf(m, __shfl_xor_sync(0xffffffffu, m, o));
    float ex = (lane < 21) ? __expf(val - m) : 0.f;
    float s = ex;
#pragma unroll
    for (int o = 16; o > 0; o >>= 1) s += __shfl_xor_sync(0xffffffffu, s, o);

    if (lane < 21) {
        out_z[v * 21 + lane] = val;
        out_pz[v * 21 + lane] = val - m - __logf(s);
    }
}

// ---------------------------------------------------------------------------

static inline int cdiv(long long a, int b) { return (int)((a + b - 1) / b); }

extern "C" void kernel_launch(void* const* d_in, const int* in_sizes, int n_in,
                              void* d_out, int out_size) {
    const float* x  = (const float*)d_in[0];
    const int*   ei = (const int*)d_in[1];
    const float* W1 = (const float*)d_in[2];  const float* b1 = (const float*)d_in[3];
    const float* W2 = (const float*)d_in[4];  const float* b2 = (const float*)d_in[5];
    const float* W3 = (const float*)d_in[6];  const float* b3 = (const float*)d_in[7];
    const float* W4 = (const float*)d_in[8];  const float* b4 = (const float*)d_in[9];

    const int n = in_sizes[0] / 21;
    const int E = in_sizes[1] / 2;

    float *bufA, *bufB, *dinv;
    __half* bufH;
    int *ideg, *row_beg, *pos, *counter;
    Edge* csr;
    cudaGetSymbolAddress((void**)&bufA, g_bufA);
    cudaGetSymbolAddress((void**)&bufB, g_bufB);
    cudaGetSymbolAddress((void**)&bufH, g_bufH);
    cudaGetSymbolAddress((void**)&dinv, g_dinv);
    cudaGetSymbolAddress((void**)&ideg, g_ideg);
    cudaGetSymbolAddress((void**)&row_beg, g_rowbeg);
    cudaGetSymbolAddress((void**)&pos, g_pos);
    cudaGetSymbolAddress((void**)&counter, g_counter);
    cudaGetSymbolAddress((void**)&csr, g_csr);

    float* out_pz = (float*)d_out;
    float* out_z  = (float*)d_out + (size_t)n * 21;

    const int T = 256;
    const int nb = cdiv(n, SCAN_B);

    // allow up to 128x168 staged A (tf32) in dynamic smem (idempotent)
    cudaFuncSetAttribute(k_gemm_tc, cudaFuncAttributeMaxDynamicSharedMemorySize,
                         168 * TAS * (int)sizeof(float));

    // --- CSR build (4 launches; scatter is atomic-free) ---
    k_init<<<cdiv(n, T), T>>>(ideg, counter, n);
    k_count_deg<<<cdiv(E, T), T>>>(ei, ideg, pos, E);
    k_offsets<<<nb, SCAN_B>>>(ideg, row_beg, dinv, csr, counter, n);
    k_scatter<<<cdiv(E, T), T>>>(ei, row_beg, pos, dinv, csr, E);

    // --- layer 1: dense agg of x (C=21, TPN=24), TC GEMM 21->168 (+bias+relu) ---
    k_agg<21, 1, 21, 24><<<cdiv((long long)n * 24, T), T>>>(
        x, row_beg, ideg, csr, dinv, nullptr, bufA, n);
    k_gemm_tc<<<cdiv(n, 128), 128, 24 * TAS * sizeof(float)>>>(
        bufA, W1, b1, bufB, nullptr, n, 21, 168, 24, 168, 1);

    // --- layer 2: TC GEMM 168->84 (fp16 t2), fp16 agg+bias+relu (C=84, VW=4) ---
    k_gemm_tc<<<cdiv(n, 128), 128, 168 * TAS * sizeof(float)>>>(
        bufB, W2, nullptr, nullptr, bufH, n, 168, 84, 168, 84, 0);
    k_agg_h<<<cdiv((long long)n * 21, T), T>>>(
        bufH, row_beg, ideg, csr, dinv, b2, bufB, n);

    // --- layer 3: TC GEMM 84->42 (out stride 44), dense agg (C=42, VW=2) ---
    k_gemm_tc<<<cdiv(n, 128), 128, 88 * TAS * sizeof(float)>>>(
        bufB, W3, nullptr, bufA, nullptr, n, 84, 42, 84, 44, 0);
    k_agg<42, 2, 44, 44><<<cdiv((long long)n * 22, T), T>>>(
        bufA, row_beg, ideg, csr, dinv, b3, bufB, n);

    // --- layer 4: scalar GEMM 42->21 (out stride 24), fused final ---
    {
        dim3 grid(cdiv(n, GBM), cdiv(21, GBN));
        k_gemm<<<grid, T>>>(bufB, W4, nullptr, bufA, n, 42, 21, 44, 24, 0);
    }
    k_final<<<cdiv((long long)n * 32, T), T>>>(
        bufA, row_beg, ideg, csr, dinv, b4, out_z, out_pz, n);
}

// round 17
// speedup vs baseline: 1.1849x; 1.1849x over previous
#include <cuda_runtime.h>
#include <cuda_fp16.h>
#include <math.h>
#include <stdint.h>

// ---------------------------------------------------------------------------
// graphNet: 4-layer GCN (21->168->84->42->21) + log_softmax.
// Round-17 = exact revert to R15 (measured best: 350.8us).
// A-resident GEMM (R16) falsified: occupancy-bound, not L2-bound.
// Config: atomic-free CSR scatter (pos captured in count pass), dense-mapped
// CSR aggs (GRP=8), fp16 t2 gather, compact tf32 TC GEMMs (layers 1-3),
// exact fp32 scalar GEMM layer 4 + fused bias/relu/log_softmax final.
// ---------------------------------------------------------------------------

#define N_MAX 100000
#define E_MAX 1600000
#define F_MAX 168
#define CSR_MAX (E_MAX + 4 * N_MAX)
#define SCAN_B 1024

struct __align__(8) Edge { int src; float w; };

__device__ float  g_bufA[(size_t)N_MAX * F_MAX];
__device__ float  g_bufB[(size_t)N_MAX * F_MAX];
__device__ __half g_bufH[(size_t)N_MAX * 84];       // t2 in fp16
__device__ int    g_ideg[N_MAX];
__device__ float  g_dinv[N_MAX];
__device__ int    g_rowbeg[N_MAX];
__device__ int    g_pos[E_MAX];                     // per-edge slot within its row
__device__ int    g_counter[1];
__device__ Edge   g_csr[CSR_MAX];

// ---------------- init / degree ----------------

__global__ void k_init(int* __restrict__ ideg, int* __restrict__ counter, int n) {
    int i = blockIdx.x * blockDim.x + threadIdx.x;
    if (i < n) ideg[i] = 0;
    if (i == 0) counter[0] = 0;
}

// counts degree AND records each edge's position within its dst row
__global__ void k_count_deg(const int* __restrict__ ei, int* __restrict__ ideg,
                            int* __restrict__ pos, int E) {
    int e = blockIdx.x * blockDim.x + threadIdx.x;
    if (e < E) pos[e] = atomicAdd(&ideg[ei[E + e]], 1);
}

// ---------------- fused single-pass offsets ----------------

__global__ void k_offsets(const int* __restrict__ ideg, int* __restrict__ row_beg,
                          float* __restrict__ dinv, Edge* __restrict__ csr,
                          int* __restrict__ counter, int n) {
    __shared__ int s[SCAN_B];
    __shared__ int base_sh;
    int i = blockIdx.x * SCAN_B + threadIdx.x;
    int deg = (i < n) ? ideg[i] : 0;
    int pd = (deg + 3) & ~3;
    s[threadIdx.x] = pd;
    __syncthreads();
#pragma unroll
    for (int off = 1; off < SCAN_B; off <<= 1) {
        int t = (threadIdx.x >= off) ? s[threadIdx.x - off] : 0;
        __syncthreads();
        s[threadIdx.x] += t;
        __syncthreads();
    }
    if (threadIdx.x == SCAN_B - 1) base_sh = atomicAdd(counter, s[SCAN_B - 1]);
    __syncthreads();
    int base = base_sh;
    if (i < n) {
        int beg = base + s[threadIdx.x] - pd;
        row_beg[i] = beg;
        dinv[i] = rsqrtf((float)(deg + 1));
        Edge z; z.src = 0; z.w = 0.f;
        for (int p = deg; p < pd; p++) csr[beg + p] = z;
    }
}

// ---------------- CSR scatter (atomic-free) ----------------

__global__ void k_scatter(const int* __restrict__ ei, const int* __restrict__ row_beg,
                          const int* __restrict__ pos, const float* __restrict__ dinv,
                          Edge* __restrict__ csr, int E) {
    int e = blockIdx.x * blockDim.x + threadIdx.x;
    if (e < E) {
        int s = ei[e];
        int d = ei[E + e];
        float2 rec = make_float2(__int_as_float(s), dinv[s] * dinv[d]);
        *reinterpret_cast<float2*>(&csr[row_beg[d] + pos[e]]) = rec;
    }
}

// ---------------- vector row load helpers ----------------

template <int VW>
__device__ __forceinline__ void ldrow(float (&f)[VW], const float* __restrict__ p) {
    if (VW == 4) { float4 t = *(const float4*)p; f[0]=t.x; f[1]=t.y; f[2]=t.z; f[3]=t.w; }
    else if (VW == 2) { float2 t = *(const float2*)p; f[0]=t.x; f[1]=t.y; }
    else { f[0] = *p; }
}

__device__ __forceinline__ void ldrow_h4(float (&f)[4], const __half* __restrict__ p) {
    uint2 u = *(const uint2*)p;                        // 4 halves, 8B aligned
    float2 a = __half22float2(*reinterpret_cast<const __half2*>(&u.x));
    float2 b = __half22float2(*reinterpret_cast<const __half2*>(&u.y));
    f[0] = a.x; f[1] = a.y; f[2] = b.x; f[3] = b.y;
}

// ---------------- fused CSR aggregation (dense thread mapping, fp32 in) --------

template <int C, int VW, int SIN, int SOUT>
__global__ void k_agg(const float* __restrict__ h, const int* __restrict__ row_beg,
                      const int* __restrict__ ideg,
                      const Edge* __restrict__ csr, const float* __restrict__ dinv,
                      const float* __restrict__ bias, float* __restrict__ out, int n) {
    constexpr int L = C / VW;
    constexpr int TPN = SOUT / VW;
    int t = blockIdx.x * blockDim.x + threadIdx.x;
    int v = t / TPN;
    int r = t - v * TPN;
    if (v >= n) return;

    if (r < L) {
        int beg = row_beg[v];
        int endp = beg + ((ideg[v] + 3) & ~3);
        const int off = r * VW;

        float dv = dinv[v];
        float pvv[VW];
        ldrow<VW>(pvv, h + v * SIN + off);

        float acc[VW];
#pragma unroll
        for (int k = 0; k < VW; k++) acc[k] = 0.f;

        int j = beg;
        for (; j + 8 <= endp; j += 8) {
            int4 e0 = *(const int4*)(csr + j);
            int4 e1 = *(const int4*)(csr + j + 2);
            int4 e2 = *(const int4*)(csr + j + 4);
            int4 e3 = *(const int4*)(csr + j + 6);
            float f[8][VW];
            ldrow<VW>(f[0], h + e0.x * SIN + off);
            ldrow<VW>(f[1], h + e0.z * SIN + off);
            ldrow<VW>(f[2], h + e1.x * SIN + off);
            ldrow<VW>(f[3], h + e1.z * SIN + off);
            ldrow<VW>(f[4], h + e2.x * SIN + off);
            ldrow<VW>(f[5], h + e2.z * SIN + off);
            ldrow<VW>(f[6], h + e3.x * SIN + off);
            ldrow<VW>(f[7], h + e3.z * SIN + off);
            float w[8];
            w[0] = __int_as_float(e0.y); w[1] = __int_as_float(e0.w);
            w[2] = __int_as_float(e1.y); w[3] = __int_as_float(e1.w);
            w[4] = __int_as_float(e2.y); w[5] = __int_as_float(e2.w);
            w[6] = __int_as_float(e3.y); w[7] = __int_as_float(e3.w);
#pragma unroll
            for (int i = 0; i < 8; i++)
#pragma unroll
                for (int k = 0; k < VW; k++) acc[k] = fmaf(w[i], f[i][k], acc[k]);
        }
        if (j < endp) {
            int4 e0 = *(const int4*)(csr + j);
            int4 e1 = *(const int4*)(csr + j + 2);
            float f[4][VW];
            ldrow<VW>(f[0], h + e0.x * SIN + off);
            ldrow<VW>(f[1], h + e0.z * SIN + off);
            ldrow<VW>(f[2], h + e1.x * SIN + off);
            ldrow<VW>(f[3], h + e1.z * SIN + off);
            float w[4];
            w[0] = __int_as_float(e0.y); w[1] = __int_as_float(e0.w);
            w[2] = __int_as_float(e1.y); w[3] = __int_as_float(e1.w);
#pragma unroll
            for (int i = 0; i < 4; i++)
#pragma unroll
                for (int k = 0; k < VW; k++) acc[k] = fmaf(w[i], f[i][k], acc[k]);
        }

        float s2 = dv * dv;
        float* po = out + v * SOUT + off;
#pragma unroll
        for (int k = 0; k < VW; k++) {
            float r2 = fmaf(s2, pvv[k], acc[k]);
            if (bias) r2 = fmaxf(r2 + bias[off + k], 0.f);
            po[k] = r2;
        }
    } else {
        float* po = out + v * SOUT + r * VW;
#pragma unroll
        for (int k = 0; k < VW; k++) po[k] = 0.f;
    }
}

// ---------------- fp16-input aggregation (layer 2: C=84, VW=4, TPN=21) --------

__global__ void k_agg_h(const __half* __restrict__ h,      // stride 84 halves
                        const int* __restrict__ row_beg,
                        const int* __restrict__ ideg,
                        const Edge* __restrict__ csr, const float* __restrict__ dinv,
                        const float* __restrict__ bias, float* __restrict__ out, int n) {
    int t = blockIdx.x * blockDim.x + threadIdx.x;
    int v = t / 21;
    int r = t - v * 21;
    if (v >= n) return;

    int beg = row_beg[v];
    int endp = beg + ((ideg[v] + 3) & ~3);
    const int off = r * 4;

    float dv = dinv[v];
    float pvv[4];
    ldrow_h4(pvv, h + v * 84 + off);

    float acc[4] = {0.f, 0.f, 0.f, 0.f};

    int j = beg;
    for (; j + 8 <= endp; j += 8) {
        int4 e0 = *(const int4*)(csr + j);
        int4 e1 = *(const int4*)(csr + j + 2);
        int4 e2 = *(const int4*)(csr + j + 4);
        int4 e3 = *(const int4*)(csr + j + 6);
        float f[8][4];
        ldrow_h4(f[0], h + e0.x * 84 + off);
        ldrow_h4(f[1], h + e0.z * 84 + off);
        ldrow_h4(f[2], h + e1.x * 84 + off);
        ldrow_h4(f[3], h + e1.z * 84 + off);
        ldrow_h4(f[4], h + e2.x * 84 + off);
        ldrow_h4(f[5], h + e2.z * 84 + off);
        ldrow_h4(f[6], h + e3.x * 84 + off);
        ldrow_h4(f[7], h + e3.z * 84 + off);
        float w[8];
        w[0] = __int_as_float(e0.y); w[1] = __int_as_float(e0.w);
        w[2] = __int_as_float(e1.y); w[3] = __int_as_float(e1.w);
        w[4] = __int_as_float(e2.y); w[5] = __int_as_float(e2.w);
        w[6] = __int_as_float(e3.y); w[7] = __int_as_float(e3.w);
#pragma unroll
        for (int i = 0; i < 8; i++)
#pragma unroll
            for (int k = 0; k < 4; k++) acc[k] = fmaf(w[i], f[i][k], acc[k]);
    }
    if (j < endp) {
        int4 e0 = *(const int4*)(csr + j);
        int4 e1 = *(const int4*)(csr + j + 2);
        float f[4][4];
        ldrow_h4(f[0], h + e0.x * 84 + off);
        ldrow_h4(f[1], h + e0.z * 84 + off);
        ldrow_h4(f[2], h + e1.x * 84 + off);
        ldrow_h4(f[3], h + e1.z * 84 + off);
        float w[4];
        w[0] = __int_as_float(e0.y); w[1] = __int_as_float(e0.w);
        w[2] = __int_as_float(e1.y); w[3] = __int_as_float(e1.w);
#pragma unroll
        for (int i = 0; i < 4; i++)
#pragma unroll
            for (int k = 0; k < 4; k++) acc[k] = fmaf(w[i], f[i][k], acc[k]);
    }

    float s2 = dv * dv;
    float* po = out + v * 84 + off;
#pragma unroll
    for (int k = 0; k < 4; k++) {
        float r2 = fmaf(s2, pvv[k], acc[k]);
        r2 = fmaxf(r2 + bias[off + k], 0.f);
        po[k] = r2;
    }
}

// ---------------- scalar GEMM (layer 4 — exact fp32) ----------------

#define GBM 256
#define GBN 32
#define GBK 16

__global__ void __launch_bounds__(256)
k_gemm(const float* __restrict__ A, const float* __restrict__ W,
       const float* __restrict__ bias, float* __restrict__ Cout,
       int N, int K, int M, int SA, int SC, int fuse_bias_relu) {
    __shared__ float As[GBK][GBM];
    __shared__ float Bs[GBK][GBN];

    int tid = threadIdx.x;
    int bm = blockIdx.x * GBM;
    int bn = blockIdx.y * GBN;
    int ty = tid >> 3;
    int tx = tid & 7;
    int row0 = ty * 8;
    int col0 = tx * 4;

    float acc[8][4];
#pragma unroll
    for (int i = 0; i < 8; i++)
#pragma unroll
        for (int j = 0; j < 4; j++) acc[i][j] = 0.f;

    for (int k0 = 0; k0 < K; k0 += GBK) {
#pragma unroll
        for (int i = 0; i < 4; i++) {
            int lin4 = tid + i * 256;
            int r = lin4 >> 2;
            int kk4 = lin4 & 3;
            int gr = bm + r;
            int gk0 = k0 + kk4 * 4;
            float4 a = make_float4(0.f, 0.f, 0.f, 0.f);
            if (gr < N && gk0 + 3 < SA)
                a = *(const float4*)(A + (size_t)gr * SA + gk0);
            As[kk4 * 4 + 0][r] = a.x;
            As[kk4 * 4 + 1][r] = a.y;
            As[kk4 * 4 + 2][r] = a.z;
            As[kk4 * 4 + 3][r] = a.w;
        }
#pragma unroll
        for (int i = 0; i < 2; i++) {
            int lin = tid + i * 256;
            int r = lin >> 5;
            int c = lin & 31;
            int gk = k0 + r, gc = bn + c;
            Bs[r][c] = (gk < K && gc < M) ? W[(size_t)gk * M + gc] : 0.f;
        }
        __syncthreads();

#pragma unroll
        for (int kk = 0; kk < GBK; kk++) {
            float4 a0 = *(const float4*)&As[kk][row0];
            float4 a1 = *(const float4*)&As[kk][row0 + 4];
            float4 b  = *(const float4*)&Bs[kk][col0];
            float av[8] = {a0.x, a0.y, a0.z, a0.w, a1.x, a1.y, a1.z, a1.w};
            float bv[4] = {b.x, b.y, b.z, b.w};
#pragma unroll
            for (int i = 0; i < 8; i++)
#pragma unroll
                for (int j = 0; j < 4; j++) acc[i][j] = fmaf(av[i], bv[j], acc[i][j]);
        }
        __syncthreads();
    }

#pragma unroll
    for (int i = 0; i < 8; i++) {
        int gr = bm + row0 + i;
        if (gr < N) {
#pragma unroll
            for (int j = 0; j < 4; j++) {
                int gc = bn + col0 + j;
                if (gc < M) {
                    float v = acc[i][j];
                    if (fuse_bias_relu) v = fmaxf(v + bias[gc], 0.f);
                    Cout[(size_t)gr * SC + gc] = v;
                }
            }
        }
    }
}

// ---------------- tf32 tensor-core GEMM (layers 1, 2, 3) ----------------

__device__ __forceinline__ uint32_t f2tf32(float x) {
    uint32_t r;
    asm("cvt.rna.tf32.f32 %0, %1;" : "=r"(r) : "f"(x));
    return r;
}

#define TAS 132   // padded smem row stride (conflict-free frag reads)

__global__ void __launch_bounds__(128)
k_gemm_tc(const float* __restrict__ A, const float* __restrict__ W,
          const float* __restrict__ bias, float* __restrict__ Cout,
          __half* __restrict__ CoutH,
          int N, int K, int M, int SA, int SC, int fuse_bias_relu) {
    __shared__ float As[8][TAS];          // [k][row], tf32-converted

    int tid = threadIdx.x;
    int warp = tid >> 5;
    int lane = tid & 31;
    int g  = lane >> 2;
    int tg = lane & 3;
    int bm = blockIdx.x * 128;
    int bn = blockIdx.y * 32;
    int wr = warp * 32;

    float c[2][4][4];
#pragma unroll
    for (int mt = 0; mt < 2; mt++)
#pragma unroll
        for (int t = 0; t < 4; t++)
#pragma unroll
            for (int q = 0; q < 4; q++) c[mt][t][q] = 0.f;

    int ksteps = (K + 7) >> 3;
    for (int ks = 0; ks < ksteps; ks++) {
        int k0 = ks << 3;
        {
            int gr = bm + tid;
            float4 a0 = make_float4(0.f, 0.f, 0.f, 0.f);
            float4 a1 = a0;
            if (gr < N) {
                const float* p = A + (size_t)gr * SA + k0;
                a0 = *(const float4*)p;
                a1 = *(const float4*)(p + 4);
            }
            As[0][tid] = __uint_as_float(f2tf32(a0.x));
            As[1][tid] = __uint_as_float(f2tf32(a0.y));
            As[2][tid] = __uint_as_float(f2tf32(a0.z));
            As[3][tid] = __uint_as_float(f2tf32(a0.w));
            As[4][tid] = __uint_as_float(f2tf32(a1.x));
            As[5][tid] = __uint_as_float(f2tf32(a1.y));
            As[6][tid] = __uint_as_float(f2tf32(a1.z));
            As[7][tid] = __uint_as_float(f2tf32(a1.w));
        }
        __syncthreads();

        uint32_t bfr[4][2];
#pragma unroll
        for (int t = 0; t < 4; t++) {
            int col = bn + t * 8 + g;
            int r0 = k0 + tg;
            int r1 = r0 + 4;
            float b0 = (r0 < K && col < M) ? W[(size_t)r0 * M + col] : 0.f;
            float b1 = (r1 < K && col < M) ? W[(size_t)r1 * M + col] : 0.f;
            bfr[t][0] = f2tf32(b0);
            bfr[t][1] = f2tf32(b1);
        }

#pragma unroll
        for (int mt = 0; mt < 2; mt++) {
            int r = wr + mt * 16 + g;
            uint32_t a0 = __float_as_uint(As[tg][r]);
            uint32_t a1 = __float_as_uint(As[tg][r + 8]);
            uint32_t a2 = __float_as_uint(As[tg + 4][r]);
            uint32_t a3 = __float_as_uint(As[tg + 4][r + 8]);
#pragma unroll
            for (int t = 0; t < 4; t++) {
                asm volatile(
                    "mma.sync.aligned.m16n8k8.row.col.f32.tf32.tf32.f32 "
                    "{%0,%1,%2,%3}, {%4,%5,%6,%7}, {%8,%9}, {%0,%1,%2,%3};"
                    : "+f"(c[mt][t][0]), "+f"(c[mt][t][1]),
                      "+f"(c[mt][t][2]), "+f"(c[mt][t][3])
                    : "r"(a0), "r"(a1), "r"(a2), "r"(a3),
                      "r"(bfr[t][0]), "r"(bfr[t][1]));
            }
        }
        __syncthreads();
    }

#pragma unroll
    for (int mt = 0; mt < 2; mt++) {
#pragma unroll
        for (int t = 0; t < 4; t++) {
            int col = bn + t * 8 + 2 * tg;
            int r0 = bm + wr + mt * 16 + g;
            float v0 = c[mt][t][0], v1 = c[mt][t][1];
            float v2 = c[mt][t][2], v3 = c[mt][t][3];
            if (fuse_bias_relu) {
                if (col < M) {
                    float bb0 = bias[col];
                    v0 = fmaxf(v0 + bb0, 0.f);
                    v2 = fmaxf(v2 + bb0, 0.f);
                }
                if (col + 1 < M) {
                    float bb1 = bias[col + 1];
                    v1 = fmaxf(v1 + bb1, 0.f);
                    v3 = fmaxf(v3 + bb1, 0.f);
                }
            }
            if (CoutH) {
                if (col + 1 < M) {
                    if (r0 < N)
                        *(__half2*)(CoutH + (size_t)r0 * SC + col) =
                            __floats2half2_rn(v0, v1);
                    if (r0 + 8 < N)
                        *(__half2*)(CoutH + (size_t)(r0 + 8) * SC + col) =
                            __floats2half2_rn(v2, v3);
                } else if (col < M) {
                    if (r0 < N) CoutH[(size_t)r0 * SC + col] = __float2half_rn(v0);
                    if (r0 + 8 < N) CoutH[(size_t)(r0 + 8) * SC + col] = __float2half_rn(v2);
                }
            } else {
                if (col + 1 < M) {
                    if (r0 < N)
                        *(float2*)(Cout + (size_t)r0 * SC + col) = make_float2(v0, v1);
                    if (r0 + 8 < N)
                        *(float2*)(Cout + (size_t)(r0 + 8) * SC + col) = make_float2(v2, v3);
                } else if (col < M) {
                    if (r0 < N) Cout[(size_t)r0 * SC + col] = v0;
                    if (r0 + 8 < N) Cout[(size_t)(r0 + 8) * SC + col] = v2;
                }
            }
        }
    }
}

// ---------------- final: CSR agg + bias + relu + log_softmax (warp/node) --------

__global__ void k_final(const float* __restrict__ t4,       // stride 24
                        const int* __restrict__ row_beg,
                        const int* __restrict__ ideg,
                        const Edge* __restrict__ csr,
                        const float* __restrict__ dinv,
                        const float* __restrict__ b4,
                        float* __restrict__ out_z, float* __restrict__ out_pz, int n) {
    int v = (blockIdx.x * blockDim.x + threadIdx.x) >> 5;
    int lane = threadIdx.x & 31;
    if (v >= n) return;

    float val = -INFINITY;
    if (lane < 21) {
        int beg = row_beg[v];
        int endp = beg + ((ideg[v] + 3) & ~3);
        float dv = dinv[v];
        float selfv = t4[v * 24 + lane];
        float acc = 0.f;

        int j = beg;
        for (; j + 8 <= endp; j += 8) {
            int4 e0 = *(const int4*)(csr + j);
            int4 e1 = *(const int4*)(csr + j + 2);
            int4 e2 = *(const int4*)(csr + j + 4);
            int4 e3 = *(const int4*)(csr + j + 6);
            float f0 = t4[e0.x * 24 + lane];
            float f1 = t4[e0.z * 24 + lane];
            float f2 = t4[e1.x * 24 + lane];
            float f3 = t4[e1.z * 24 + lane];
            float f4 = t4[e2.x * 24 + lane];
            float f5 = t4[e2.z * 24 + lane];
            float f6 = t4[e3.x * 24 + lane];
            float f7 = t4[e3.z * 24 + lane];
            acc = fmaf(__int_as_float(e0.y), f0, acc);
            acc = fmaf(__int_as_float(e0.w), f1, acc);
            acc = fmaf(__int_as_float(e1.y), f2, acc);
            acc = fmaf(__int_as_float(e1.w), f3, acc);
            acc = fmaf(__int_as_float(e2.y), f4, acc);
            acc = fmaf(__int_as_float(e2.w), f5, acc);
            acc = fmaf(__int_as_float(e3.y), f6, acc);
            acc = fmaf(__int_as_float(e3.w), f7, acc);
        }
        if (j < endp) {
            int4 e0 = *(const int4*)(csr + j);
            int4 e1 = *(const int4*)(csr + j + 2);
            float f0 = t4[e0.x * 24 + lane];
            float f1 = t4[e0.z * 24 + lane];
            float f2 = t4[e1.x * 24 + lane];
            float f3 = t4[e1.z * 24 + lane];
            acc = fmaf(__int_as_float(e0.y), f0, acc);
            acc = fmaf(__int_as_float(e0.w), f1, acc);
            acc = fmaf(__int_as_float(e1.y), f2, acc);
            acc = fmaf(__int_as_float(e1.w), f3, acc);
        }
        acc = fmaf(dv * dv, selfv, acc);
        val = fmaxf(acc + b4[lane], 0.f);
    }

    float m = val;
#pragma unroll
    for (int o = 16; o > 0; o >>= 1) m = fmaxf(m, __shfl_xor_sync(0xffffffffu, m, o));
    float ex = (lane < 21) ? __expf(val - m) : 0.f;
    float s = ex;
#pragma unroll
    for (int o = 16; o > 0; o >>= 1) s += __shfl_xor_sync(0xffffffffu, s, o);

    if (lane < 21) {
        out_z[v * 21 + lane] = val;
        out_pz[v * 21 + lane] = val - m - __logf(s);
    }
}

// ---------------------------------------------------------------------------

static inline int cdiv(long long a, int b) { return (int)((a + b - 1) / b); }

extern "C" void kernel_launch(void* const* d_in, const int* in_sizes, int n_in,
                              void* d_out, int out_size) {
    const float* x  = (const float*)d_in[0];
    const int*   ei = (const int*)d_in[1];
    const float* W1 = (const float*)d_in[2];  const float* b1 = (const float*)d_in[3];
    const float* W2 = (const float*)d_in[4];  const float* b2 = (const float*)d_in[5];
    const float* W3 = (const float*)d_in[6];  const float* b3 = (const float*)d_in[7];
    const float* W4 = (const float*)d_in[8];  const float* b4 = (const float*)d_in[9];

    const int n = in_sizes[0] / 21;
    const int E = in_sizes[1] / 2;

    float *bufA, *bufB, *dinv;
    __half* bufH;
    int *ideg, *row_beg, *pos, *counter;
    Edge* csr;
    cudaGetSymbolAddress((void**)&bufA, g_bufA);
    cudaGetSymbolAddress((void**)&bufB, g_bufB);
    cudaGetSymbolAddress((void**)&bufH, g_bufH);
    cudaGetSymbolAddress((void**)&dinv, g_dinv);
    cudaGetSymbolAddress((void**)&ideg, g_ideg);
    cudaGetSymbolAddress((void**)&row_beg, g_rowbeg);
    cudaGetSymbolAddress((void**)&pos, g_pos);
    cudaGetSymbolAddress((void**)&counter, g_counter);
    cudaGetSymbolAddress((void**)&csr, g_csr);

    float* out_pz = (float*)d_out;
    float* out_z  = (float*)d_out + (size_t)n * 21;

    const int T = 256;
    const int nb = cdiv(n, SCAN_B);

    // --- CSR build (4 launches; scatter is atomic-free) ---
    k_init<<<cdiv(n, T), T>>>(ideg, counter, n);
    k_count_deg<<<cdiv(E, T), T>>>(ei, ideg, pos, E);
    k_offsets<<<nb, SCAN_B>>>(ideg, row_beg, dinv, csr, counter, n);
    k_scatter<<<cdiv(E, T), T>>>(ei, row_beg, pos, dinv, csr, E);

    // --- layer 1: dense agg of x (C=21, TPN=24), TC GEMM 21->168 (+bias+relu) ---
    k_agg<21, 1, 21, 24><<<cdiv((long long)n * 24, T), T>>>(
        x, row_beg, ideg, csr, dinv, nullptr, bufA, n);
    {
        dim3 grid(cdiv(n, 128), cdiv(168, 32));
        k_gemm_tc<<<grid, 128>>>(bufA, W1, b1, bufB, nullptr, n, 21, 168, 24, 168, 1);
    }
    // --- layer 2: TC GEMM 168->84 (fp16 t2), fp16 agg+bias+relu (C=84, VW=4) ---
    {
        dim3 grid(cdiv(n, 128), cdiv(84, 32));
        k_gemm_tc<<<grid, 128>>>(bufB, W2, nullptr, nullptr, bufH, n, 168, 84, 168, 84, 0);
    }
    k_agg_h<<<cdiv((long long)n * 21, T), T>>>(
        bufH, row_beg, ideg, csr, dinv, b2, bufB, n);
    // --- layer 3: TC GEMM 84->42 (out stride 44), dense agg (C=42, VW=2) ---
    {
        dim3 grid(cdiv(n, 128), cdiv(42, 32));
        k_gemm_tc<<<grid, 128>>>(bufB, W3, nullptr, bufA, nullptr, n, 84, 42, 84, 44, 0);
    }
    k_agg<42, 2, 44, 44><<<cdiv((long long)n * 22, T), T>>>(
        bufA, row_beg, ideg, csr, dinv, b3, bufB, n);
    // --- layer 4: scalar GEMM 42->21 (out stride 24), fused final ---
    {
        dim3 grid(cdiv(n, GBM), cdiv(21, GBN));
        k_gemm<<<grid, T>>>(bufB, W4, nullptr, bufA, n, 42, 21, 44, 24, 0);
    }
    k_final<<<cdiv((long long)n * 32, T), T>>>(
        bufA, row_beg, ideg, csr, dinv, b4, out_z, out_pz, n);
}